// round 15
// baseline (speedup 1.0000x reference)
#include <cuda_runtime.h>
#include <cuda_fp16.h>
#include <mma.h>
#include <cstdint>
#include <cstddef>

using namespace nvcuda;

// Problem constants
constexpr int Bc = 8, Tc = 512, Vc = 24, Dc = 512, Hc = 8, DHc = 64, DFFc = 2048;
constexpr int BV = Bc * Vc;              // 192
constexpr int MTOK = BV * Tc;            // 98304 tokens

// ---------------- scratch (device globals; allocation-free rule) ----------------
__device__ __half g_xnh [(size_t)MTOK * Dc];    // LN1 out (half)
__device__ __half g_qh  [(size_t)MTOK * Dc];    // Q head-major (half)
__device__ __half g_kh  [(size_t)MTOK * Dc];
__device__ __half g_vh  [(size_t)MTOK * Dc];
__device__ __half g_ath [(size_t)MTOK * Dc];    // attention out (half)
__device__ __half g_h2h [(size_t)MTOK * Dc];    // LN2 out (half)
__device__ __half g_ffh [(size_t)MTOK * DFFc];  // FFN hidden (half)
__device__ float  g_xr  [(size_t)MTOK * Dc];    // residual stream (fp32)
// half weights
__device__ __half g_wqkv[Dc * 3 * Dc];          // [K=512][N=1536] concat Q|K|V
__device__ float  g_bqkv[3 * Dc];               // concat biases
__device__ __half g_who[Dc * Dc];
__device__ __half g_wh1[Dc * DFFc];
__device__ __half g_wh2[DFFc * Dc];

// ---------------- helpers ----------------
__device__ __forceinline__ void cp_async16(void* smem, const void* g) {
    uint32_t s = (uint32_t)__cvta_generic_to_shared(smem);
    asm volatile("cp.async.cg.shared.global [%0], [%1], 16;\n" :: "r"(s), "l"(g));
}
__device__ __forceinline__ void cp_commit() { asm volatile("cp.async.commit_group;\n"); }
template <int N>
__device__ __forceinline__ void cp_wait() { asm volatile("cp.async.wait_group %0;\n" :: "n"(N)); }

// ---------------- weight fp32 -> fp16 (one-shot, tiny) ----------------
__global__ void wconv(const float* __restrict__ in, __half* __restrict__ out, int n4)
{
    int i = blockIdx.x * 256 + threadIdx.x;
    if (i < n4) {
        float4 v = reinterpret_cast<const float4*>(in)[i];
        reinterpret_cast<__half2*>(out)[i * 2]     = __floats2half2_rn(v.x, v.y);
        reinterpret_cast<__half2*>(out)[i * 2 + 1] = __floats2half2_rn(v.z, v.w);
    }
}
// in [512][512] -> out rows of ld=1536 at column offset off
__global__ void wconv_off(const float* __restrict__ in, __half* __restrict__ out,
                          int off)
{
    int i = blockIdx.x * 256 + threadIdx.x;   // over 512*512/4
    if (i < Dc * Dc / 4) {
        int k = (i * 4) >> 9, n = (i * 4) & 511;
        float4 v = reinterpret_cast<const float4*>(in)[i];
        __half2* o = reinterpret_cast<__half2*>(out + (size_t)k * (3 * Dc) + off + n);
        o[0] = __floats2half2_rn(v.x, v.y);
        o[1] = __floats2half2_rn(v.z, v.w);
    }
}
__global__ void bcat(const float* __restrict__ a, const float* __restrict__ b,
                     const float* __restrict__ c, float* __restrict__ o)
{
    int i = blockIdx.x * 256 + threadIdx.x;
    if (i < Dc) { o[i] = a[i]; o[Dc + i] = b[i]; o[2 * Dc + i] = c[i]; }
}

// ---------------- LayerNorm: one warp per token, half output ----------------
__global__ void ln_kernel(const float* __restrict__ in, const float* __restrict__ g,
                          const float* __restrict__ be, __half* __restrict__ out, int trans)
{
    int tid = threadIdx.x, wid = tid >> 5, lane = tid & 31;
    int m = blockIdx.x * 8 + wid;
    const float* row;
    if (trans) {
        int bv = m >> 9, t = m & 511;
        int b = bv / Vc, v = bv % Vc;
        row = in + ((size_t)((b * Tc + t) * Vc + v)) * Dc;
    } else {
        row = in + (size_t)m * Dc;
    }
    float4 x4[4];
    float sum = 0.f, sq = 0.f;
#pragma unroll
    for (int j = 0; j < 4; j++) {
        x4[j] = reinterpret_cast<const float4*>(row)[lane + 32 * j];
        sum += x4[j].x + x4[j].y + x4[j].z + x4[j].w;
        sq  += x4[j].x * x4[j].x + x4[j].y * x4[j].y + x4[j].z * x4[j].z + x4[j].w * x4[j].w;
    }
#pragma unroll
    for (int o = 16; o > 0; o >>= 1) {
        sum += __shfl_xor_sync(0xffffffffu, sum, o);
        sq  += __shfl_xor_sync(0xffffffffu, sq,  o);
    }
    float mean = sum * (1.f / Dc);
    float var  = sq * (1.f / Dc) - mean * mean;
    float rstd = rsqrtf(var + 1e-5f);
    __half2* orow = reinterpret_cast<__half2*>(out + (size_t)m * Dc);
#pragma unroll
    for (int j = 0; j < 4; j++) {
        int f4 = lane + 32 * j;
        float4 gv = reinterpret_cast<const float4*>(g)[f4];
        float4 bb = reinterpret_cast<const float4*>(be)[f4];
        float ox = (x4[j].x - mean) * rstd * gv.x + bb.x;
        float oy = (x4[j].y - mean) * rstd * gv.y + bb.y;
        float oz = (x4[j].z - mean) * rstd * gv.z + bb.z;
        float ow = (x4[j].w - mean) * rstd * gv.w + bb.w;
        orow[f4 * 2]     = __floats2half2_rn(ox, oy);
        orow[f4 * 2 + 1] = __floats2half2_rn(oz, ow);
    }
}

// ---------------- fp16 wmma GEMM: BM=256, warp tile 64x64, 3-stage ring ----------------
// EPI 0: merged QKV (N=1536) -> q/k/v head-major half
// EPI 1: Oproj -> outf[m*D+n] = v + bias + x_src(transposed gather)
// EPI 2: FFN1  -> outh[m*N+n] = half(gelu(v + bias))
// EPI 3: FFN2  -> outf[((b*T+t)*V+v)*D+n] = v + bias + resid[m*D+n]
constexpr int BM = 256, BN = 128, BKg = 64, NST = 3;
constexpr int ALDh = 72, BLDh = 136, SLDg = 136;
constexpr int ASTGh = BM * ALDh;          // 18432 halves / stage
constexpr int BSTGh = BKg * BLDh;         // 8704 halves / stage
constexpr size_t SMH = (size_t)NST * (ASTGh + BSTGh) * sizeof(__half);   // 162816 B

template <int EPI>
__global__ void __launch_bounds__(256, 1)
gemm_h(const __half* __restrict__ A, const __half* __restrict__ B,
       int M, int N, int K,
       const float* __restrict__ bias,
       const float* __restrict__ aux,
       float* __restrict__ outf, __half* __restrict__ outh,
       __half* __restrict__ outh2, __half* __restrict__ outh3)
{
    extern __shared__ char smraw[];
    __half* hbase = reinterpret_cast<__half*>(smraw);
    const int tid = threadIdx.x, wid = tid >> 5;
    const int wm = wid & 3, wn = wid >> 2;          // 4x2 warp grid, warp tile 64x64
    const int m0 = blockIdx.y * BM, n0 = blockIdx.x * BN;

    wmma::fragment<wmma::accumulator, 16, 16, 16, float> acc[4][4];
#pragma unroll
    for (int i = 0; i < 4; i++)
#pragma unroll
        for (int j = 0; j < 4; j++) wmma::fill_fragment(acc[i][j], 0.0f);

    auto load_stage = [&](int k0, int b) {
        __half* As = hbase + b * ASTGh;
        __half* Bs = hbase + NST * ASTGh + b * BSTGh;
#pragma unroll
        for (int i = 0; i < 8; i++) {               // A: 256x64 halves = 2048 x 16B
            int f = tid + 256 * i;
            int r = f >> 3, c = f & 7;
            cp_async16(As + r * ALDh + c * 8, A + (size_t)(m0 + r) * K + k0 + c * 8);
        }
#pragma unroll
        for (int i = 0; i < 4; i++) {               // B: 64x128 halves = 1024 x 16B
            int f = tid + 256 * i;
            int r = f >> 4, c = f & 15;
            cp_async16(Bs + r * BLDh + c * 8, B + (size_t)(k0 + r) * N + n0 + c * 8);
        }
    };

    const int nst = K / BKg;
    load_stage(0, 0); cp_commit();
    load_stage(BKg, 1); cp_commit();

    for (int s = 0; s < nst; s++) {
        if (s < nst - 1) cp_wait<1>(); else cp_wait<0>();
        __syncthreads();
        if (s + 2 < nst) { load_stage((s + 2) * BKg, (s + 2) % NST); cp_commit(); }

        const __half* As = hbase + (s % NST) * ASTGh;
        const __half* Bs = hbase + NST * ASTGh + (s % NST) * BSTGh;
#pragma unroll
        for (int kk = 0; kk < BKg; kk += 16) {
            wmma::fragment<wmma::matrix_a, 16, 16, 16, __half, wmma::row_major> af[4];
            wmma::fragment<wmma::matrix_b, 16, 16, 16, __half, wmma::row_major> bf[4];
#pragma unroll
            for (int i = 0; i < 4; i++)
                wmma::load_matrix_sync(af[i], As + (wm * 64 + i * 16) * ALDh + kk, ALDh);
#pragma unroll
            for (int j = 0; j < 4; j++)
                wmma::load_matrix_sync(bf[j], Bs + kk * BLDh + wn * 64 + j * 16, BLDh);
#pragma unroll
            for (int i = 0; i < 4; i++)
#pragma unroll
                for (int j = 0; j < 4; j++)
                    wmma::mma_sync(acc[i][j], af[i], bf[j], acc[i][j]);
        }
    }
    __syncthreads();   // drain before reusing smem as fp32 staging

    float* St = reinterpret_cast<float*>(smraw);    // [256][136] = 139264 B <= SMH
#pragma unroll
    for (int i = 0; i < 4; i++)
#pragma unroll
        for (int j = 0; j < 4; j++)
            wmma::store_matrix_sync(St + (wm * 64 + i * 16) * SLDg + wn * 64 + j * 16,
                                    acc[i][j], SLDg, wmma::mem_row_major);
    __syncthreads();

    for (int idx = tid; idx < BM * BN; idx += 256) {
        int r = idx >> 7, c = idx & 127;
        float v = St[r * SLDg + c];
        int gm = m0 + r, gn = n0 + c;
        v += bias[gn];
        if (EPI == 0) {
            int bv = gm >> 9, t = gm & 511;
            int which = gn >> 9, n = gn & 511, h = n >> 6, dh = n & 63;
            __half* dst = (which == 0) ? outh : (which == 1) ? outh2 : outh3;
            dst[(((size_t)(bv * Hc + h) * Tc + t) << 6) + dh] = __float2half(v);
        } else if (EPI == 1) {
            int bv = gm >> 9, t = gm & 511, b2 = bv / Vc, vv = bv % Vc;
            v += aux[((size_t)((b2 * Tc + t) * Vc + vv) << 9) + gn];
            outf[((size_t)gm << 9) + gn] = v;
        } else if (EPI == 2) {
            v = 0.5f * v * (1.0f + erff(v * 0.70710678118654752f));
            outh[(size_t)gm * N + gn] = __float2half(v);
        } else {
            int bv = gm >> 9, t = gm & 511, b2 = bv / Vc, vv = bv % Vc;
            v += aux[((size_t)gm << 9) + gn];
            outf[((size_t)((b2 * Tc + t) * Vc + vv) << 9) + gn] = v;
        }
    }
}

// ---------------- Attention: fp16 operands, 128-row K/V chunks (R12 proven) ----------------
constexpr int QB = 32, CK = 128, KLDh = 72, SLDa = 520;
constexpr int OS_S  = 0;                           // 32*520 fp32
constexpr int OS_Q  = QB * SLDa;                   // Q: 32*72 halves = 1152 floats
constexpr int OS_KV = OS_Q + (QB * KLDh) / 2;      // KV: 2 x 128*72 halves = 9216 floats
constexpr int OS_MB = OS_KV + (2 * CK * KLDh) / 2;
constexpr size_t SMA = (size_t)(OS_MB + Tc) * sizeof(float);   // 110080 B

__global__ void __launch_bounds__(256, 2)
attn_kernel(const __half* __restrict__ Q, const __half* __restrict__ K,
            const __half* __restrict__ V, const int* __restrict__ mask,
            __half* __restrict__ out)
{
    extern __shared__ float f[];
    __half* hq  = reinterpret_cast<__half*>(f + OS_Q);
    __half* hkv = reinterpret_cast<__half*>(f + OS_KV);
    __half* hp  = reinterpret_cast<__half*>(f);          // probs overlay on scores
    const int tid = threadIdx.x, wid = tid >> 5, lane = tid & 31;
    const int q0 = blockIdx.x * QB, h = blockIdx.y, bv = blockIdx.z, b = bv / Vc;
    const __half* Qh = Q + (size_t)(bv * Hc + h) * Tc * DHc;
    const __half* Kh = K + (size_t)(bv * Hc + h) * Tc * DHc;
    const __half* Vh = V + (size_t)(bv * Hc + h) * Tc * DHc;
    const int tm = wid & 1, tn = wid >> 1;   // 2x4 warp tiles over 32x64

    if (tid < 256) {
        int r = tid >> 3, c = tid & 7;
        cp_async16(hq + r * KLDh + c * 8, Qh + (size_t)(q0 + r) * DHc + c * 8);
    }
#pragma unroll
    for (int i = 0; i < 4; i++) {
        int fi = tid + 256 * i; int r = fi >> 3, c = fi & 7;
        cp_async16(hkv + r * KLDh + c * 8, Kh + (size_t)r * DHc + c * 8);
    }
    cp_commit();
    for (int j = tid; j < Tc; j += 256)
        f[OS_MB + j] = (mask[(size_t)b * Tc + j] != 0) ? 0.f : -INFINITY;

    // ---- Phase A: S = Q K^T / 8, 4 chunks of 128 keys ----
    for (int c = 0; c < 4; c++) {
        if (c + 1 < 4) {
            const __half* src = Kh + (size_t)(c + 1) * CK * DHc;
            __half* dst = hkv + ((c + 1) & 1) * (CK * KLDh);
#pragma unroll
            for (int i = 0; i < 4; i++) {
                int fi = tid + 256 * i; int r = fi >> 3, cc = fi & 7;
                cp_async16(dst + r * KLDh + cc * 8, src + (size_t)r * DHc + cc * 8);
            }
            cp_commit();
            cp_wait<1>();
        } else cp_wait<0>();
        __syncthreads();

        const __half* kb = hkv + (c & 1) * (CK * KLDh);
#pragma unroll
        for (int sub = 0; sub < 2; sub++) {
            wmma::fragment<wmma::accumulator, 16, 16, 16, float> acc;
            wmma::fill_fragment(acc, 0.0f);
#pragma unroll
            for (int kk = 0; kk < DHc; kk += 16) {
                wmma::fragment<wmma::matrix_a, 16, 16, 16, __half, wmma::row_major> af;
                wmma::fragment<wmma::matrix_b, 16, 16, 16, __half, wmma::col_major> bf;
                wmma::load_matrix_sync(af, hq + (tm * 16) * KLDh + kk, KLDh);
                wmma::load_matrix_sync(bf, kb + (tn * 32 + sub * 16) * KLDh + kk, KLDh);
                wmma::mma_sync(acc, af, bf, acc);
            }
#pragma unroll
            for (int e = 0; e < acc.num_elements; e++) acc.x[e] *= 0.125f;
            wmma::store_matrix_sync(f + OS_S + (tm * 16) * SLDa + c * 128 + tn * 32 + sub * 16,
                                    acc, SLDa, wmma::mem_row_major);
        }
        __syncthreads();
    }

    // prefetch V chunk 0 under softmax
#pragma unroll
    for (int i = 0; i < 4; i++) {
        int fi = tid + 256 * i; int r = fi >> 3, cc = fi & 7;
        cp_async16(hkv + r * KLDh + cc * 8, Vh + (size_t)r * DHc + cc * 8);
    }
    cp_commit();

    // ---- softmax: each warp owns 4 rows; probs written back as half ----
#pragma unroll
    for (int rr = 0; rr < 4; rr++) {
        int row = wid * 4 + rr;
        float* basep = f + OS_S + row * SLDa;
        float vv[16];
        float mx = -INFINITY;
#pragma unroll
        for (int jj = 0; jj < 16; jj++) {
            int j = lane + 32 * jj;
            vv[jj] = basep[j] + f[OS_MB + j];
            mx = fmaxf(mx, vv[jj]);
        }
#pragma unroll
        for (int o = 16; o > 0; o >>= 1) mx = fmaxf(mx, __shfl_xor_sync(0xffffffffu, mx, o));
        float sum = 0.f;
#pragma unroll
        for (int jj = 0; jj < 16; jj++) { vv[jj] = __expf(vv[jj] - mx); sum += vv[jj]; }
#pragma unroll
        for (int o = 16; o > 0; o >>= 1) sum += __shfl_xor_sync(0xffffffffu, sum, o);
        float inv = 1.f / sum;
        __half* hrow = hp + (size_t)row * (SLDa * 2);
#pragma unroll
        for (int jj = 0; jj < 16; jj++) hrow[lane + 32 * jj] = __float2half(vv[jj] * inv);
    }
    __syncthreads();

    // ---- Phase B: O = P V, 4 chunks of 128 keys ----
    wmma::fragment<wmma::accumulator, 16, 16, 16, float> accO;
    wmma::fill_fragment(accO, 0.0f);
    for (int c = 0; c < 4; c++) {
        if (c + 1 < 4) {
            const __half* src = Vh + (size_t)(c + 1) * CK * DHc;
            __half* dst = hkv + ((c + 1) & 1) * (CK * KLDh);
#pragma unroll
            for (int i = 0; i < 4; i++) {
                int fi = tid + 256 * i; int r = fi >> 3, cc = fi & 7;
                cp_async16(dst + r * KLDh + cc * 8, src + (size_t)r * DHc + cc * 8);
            }
            cp_commit();
            cp_wait<1>();
        } else cp_wait<0>();
        __syncthreads();

        const __half* vb = hkv + (c & 1) * (CK * KLDh);
#pragma unroll
        for (int kk = 0; kk < CK; kk += 16) {
            wmma::fragment<wmma::matrix_a, 16, 16, 16, __half, wmma::row_major> af;
            wmma::fragment<wmma::matrix_b, 16, 16, 16, __half, wmma::row_major> bf;
            wmma::load_matrix_sync(af, hp + (size_t)(tm * 16) * (SLDa * 2) + c * 128 + kk,
                                   SLDa * 2);
            wmma::load_matrix_sync(bf, vb + kk * KLDh + tn * 16, KLDh);
            wmma::mma_sync(accO, af, bf, accO);
        }
        __syncthreads();
    }

    float* St2 = f + OS_S;          // [32][68]
    wmma::store_matrix_sync(St2 + (tm * 16) * 68 + tn * 16, accO, 68, wmma::mem_row_major);
    __syncthreads();
    for (int idx = tid; idx < QB * 64; idx += 256) {
        int r = idx >> 6, c = idx & 63;
        out[(size_t)(bv * Tc + q0 + r) * Dc + h * DHc + c] = __float2half(St2[r * 68 + c]);
    }
}

// ---------------- launch ----------------
extern "C" void kernel_launch(void* const* d_in, const int* in_sizes, int n_in,
                              void* d_out, int out_size)
{
    const float* x  = (const float*)d_in[0];
    const int* mask = (const int*)d_in[1];          // bool -> int32 in harness
    const float* Wq = (const float*)d_in[2];
    const float* bq = (const float*)d_in[3];
    const float* Wk = (const float*)d_in[4];
    const float* bk = (const float*)d_in[5];
    const float* Wv = (const float*)d_in[6];
    const float* bvb = (const float*)d_in[7];
    const float* Wo = (const float*)d_in[8];
    const float* bo = (const float*)d_in[9];
    const float* W1 = (const float*)d_in[10];
    const float* b1 = (const float*)d_in[11];
    const float* W2 = (const float*)d_in[12];
    const float* b2 = (const float*)d_in[13];
    const float* g1 = (const float*)d_in[14];
    const float* be1 = (const float*)d_in[15];
    const float* g2 = (const float*)d_in[16];
    const float* be2 = (const float*)d_in[17];
    float* out = (float*)d_out;

    __half *xnh, *qh, *kh, *vh, *ath, *h2h, *ffh, *wqkv, *who, *wh1, *wh2;
    float *xr, *bqkv;
    cudaGetSymbolAddress((void**)&xnh,  g_xnh);
    cudaGetSymbolAddress((void**)&qh,   g_qh);
    cudaGetSymbolAddress((void**)&kh,   g_kh);
    cudaGetSymbolAddress((void**)&vh,   g_vh);
    cudaGetSymbolAddress((void**)&ath,  g_ath);
    cudaGetSymbolAddress((void**)&h2h,  g_h2h);
    cudaGetSymbolAddress((void**)&ffh,  g_ffh);
    cudaGetSymbolAddress((void**)&xr,   g_xr);
    cudaGetSymbolAddress((void**)&wqkv, g_wqkv);
    cudaGetSymbolAddress((void**)&bqkv, g_bqkv);
    cudaGetSymbolAddress((void**)&who,  g_who);
    cudaGetSymbolAddress((void**)&wh1,  g_wh1);
    cudaGetSymbolAddress((void**)&wh2,  g_wh2);

    cudaFuncSetAttribute(gemm_h<0>, cudaFuncAttributeMaxDynamicSharedMemorySize, (int)SMH);
    cudaFuncSetAttribute(gemm_h<1>, cudaFuncAttributeMaxDynamicSharedMemorySize, (int)SMH);
    cudaFuncSetAttribute(gemm_h<2>, cudaFuncAttributeMaxDynamicSharedMemorySize, (int)SMH);
    cudaFuncSetAttribute(gemm_h<3>, cudaFuncAttributeMaxDynamicSharedMemorySize, (int)SMH);
    cudaFuncSetAttribute(attn_kernel, cudaFuncAttributeMaxDynamicSharedMemorySize, (int)SMA);

    // 0. weights fp32 -> fp16 (QKV concatenated into [512][1536])
    wconv_off<<<Dc * Dc / 4 / 256, 256>>>(Wq, wqkv, 0);
    wconv_off<<<Dc * Dc / 4 / 256, 256>>>(Wk, wqkv, Dc);
    wconv_off<<<Dc * Dc / 4 / 256, 256>>>(Wv, wqkv, 2 * Dc);
    bcat<<<2, 256>>>(bq, bk, bvb, bqkv);
    wconv<<<Dc * Dc / 4 / 256, 256>>>(Wo, who, Dc * Dc / 4);
    wconv<<<Dc * DFFc / 4 / 256, 256>>>(W1, wh1, Dc * DFFc / 4);
    wconv<<<DFFc * Dc / 4 / 256, 256>>>(W2, wh2, DFFc * Dc / 4);

    dim3 gqkv(3 * Dc / BN, MTOK / BM);   // (12, 384)
    dim3 g512(Dc / BN, MTOK / BM);       // (4, 384)
    dim3 gff(DFFc / BN, MTOK / BM);      // (16, 384)

    // 1. LN1 (gather-transpose from x) -> half
    ln_kernel<<<MTOK / 8, 256>>>(x, g1, be1, xnh, 1);
    // 2. merged QKV projection -> head-major half
    gemm_h<0><<<gqkv, 256, SMH>>>(xnh, wqkv, MTOK, 3 * Dc, Dc, bqkv, nullptr,
                                  nullptr, qh, kh, vh);
    // 3. Attention -> half
    attn_kernel<<<dim3(Tc / QB, Hc, BV), 256, SMA>>>(qh, kh, vh, mask, ath);
    // 4. O-projection + residual (x gathered) -> xr fp32
    gemm_h<1><<<g512, 256, SMH>>>(ath, who, MTOK, Dc, Dc, bo, x, xr, nullptr,
                                  nullptr, nullptr);
    // 5. LN2 -> half
    ln_kernel<<<MTOK / 8, 256>>>(xr, g2, be2, h2h, 0);
    // 6. FFN1 + bias + exact gelu -> half
    gemm_h<2><<<gff, 256, SMH>>>(h2h, wh1, MTOK, DFFc, Dc, b1, nullptr,
                                 nullptr, ffh, nullptr, nullptr);
    // 7. FFN2 + bias + residual + scatter-transpose -> fp32 d_out
    gemm_h<3><<<g512, 256, SMH>>>(ffh, wh2, MTOK, Dc, DFFc, b2, xr, out,
                                  nullptr, nullptr, nullptr);
}

// round 16
// speedup vs baseline: 1.2964x; 1.2964x over previous
#include <cuda_runtime.h>
#include <cuda_fp16.h>
#include <mma.h>
#include <cstdint>
#include <cstddef>

using namespace nvcuda;

// Problem constants
constexpr int Bc = 8, Tc = 512, Vc = 24, Dc = 512, Hc = 8, DHc = 64, DFFc = 2048;
constexpr int BV = Bc * Vc;              // 192
constexpr int MTOK = BV * Tc;            // 98304 tokens

// ---------------- scratch (device globals; allocation-free rule) ----------------
__device__ __half g_xnh [(size_t)MTOK * Dc];    // LN1 out (half)
__device__ __half g_qh  [(size_t)MTOK * Dc];    // Q head-major (half)
__device__ __half g_kh  [(size_t)MTOK * Dc];
__device__ __half g_vh  [(size_t)MTOK * Dc];
__device__ __half g_ath [(size_t)MTOK * Dc];    // attention out (half)
__device__ __half g_h2h [(size_t)MTOK * Dc];    // LN2 out (half)
__device__ __half g_ffh [(size_t)MTOK * DFFc];  // FFN hidden (half)
__device__ float  g_xr  [(size_t)MTOK * Dc];    // residual stream (fp32)
// half weights
__device__ __half g_wqkv[Dc * 3 * Dc];          // [K=512][N=1536] concat Q|K|V
__device__ float  g_bqkv[3 * Dc];               // concat biases
__device__ __half g_who[Dc * Dc];
__device__ __half g_wh1[Dc * DFFc];
__device__ __half g_wh2[DFFc * Dc];

// ---------------- helpers ----------------
__device__ __forceinline__ void cp_async16(void* smem, const void* g) {
    uint32_t s = (uint32_t)__cvta_generic_to_shared(smem);
    asm volatile("cp.async.cg.shared.global [%0], [%1], 16;\n" :: "r"(s), "l"(g));
}
__device__ __forceinline__ void cp_commit() { asm volatile("cp.async.commit_group;\n"); }
template <int N>
__device__ __forceinline__ void cp_wait() { asm volatile("cp.async.wait_group %0;\n" :: "n"(N)); }

// ---------------- weight fp32 -> fp16 (one-shot, tiny) ----------------
__global__ void wconv(const float* __restrict__ in, __half* __restrict__ out, int n4)
{
    int i = blockIdx.x * 256 + threadIdx.x;
    if (i < n4) {
        float4 v = reinterpret_cast<const float4*>(in)[i];
        reinterpret_cast<__half2*>(out)[i * 2]     = __floats2half2_rn(v.x, v.y);
        reinterpret_cast<__half2*>(out)[i * 2 + 1] = __floats2half2_rn(v.z, v.w);
    }
}
// in [512][512] -> out rows of ld=1536 at column offset off
__global__ void wconv_off(const float* __restrict__ in, __half* __restrict__ out,
                          int off)
{
    int i = blockIdx.x * 256 + threadIdx.x;   // over 512*512/4
    if (i < Dc * Dc / 4) {
        int k = (i * 4) >> 9, n = (i * 4) & 511;
        float4 v = reinterpret_cast<const float4*>(in)[i];
        __half2* o = reinterpret_cast<__half2*>(out + (size_t)k * (3 * Dc) + off + n);
        o[0] = __floats2half2_rn(v.x, v.y);
        o[1] = __floats2half2_rn(v.z, v.w);
    }
}
__global__ void bcat(const float* __restrict__ a, const float* __restrict__ b,
                     const float* __restrict__ c, float* __restrict__ o)
{
    int i = blockIdx.x * 256 + threadIdx.x;
    if (i < Dc) { o[i] = a[i]; o[Dc + i] = b[i]; o[2 * Dc + i] = c[i]; }
}

// ---------------- LayerNorm: one warp per token, half output ----------------
__global__ void ln_kernel(const float* __restrict__ in, const float* __restrict__ g,
                          const float* __restrict__ be, __half* __restrict__ out, int trans)
{
    int tid = threadIdx.x, wid = tid >> 5, lane = tid & 31;
    int m = blockIdx.x * 8 + wid;
    const float* row;
    if (trans) {
        int bv = m >> 9, t = m & 511;
        int b = bv / Vc, v = bv % Vc;
        row = in + ((size_t)((b * Tc + t) * Vc + v)) * Dc;
    } else {
        row = in + (size_t)m * Dc;
    }
    float4 x4[4];
    float sum = 0.f, sq = 0.f;
#pragma unroll
    for (int j = 0; j < 4; j++) {
        x4[j] = reinterpret_cast<const float4*>(row)[lane + 32 * j];
        sum += x4[j].x + x4[j].y + x4[j].z + x4[j].w;
        sq  += x4[j].x * x4[j].x + x4[j].y * x4[j].y + x4[j].z * x4[j].z + x4[j].w * x4[j].w;
    }
#pragma unroll
    for (int o = 16; o > 0; o >>= 1) {
        sum += __shfl_xor_sync(0xffffffffu, sum, o);
        sq  += __shfl_xor_sync(0xffffffffu, sq,  o);
    }
    float mean = sum * (1.f / Dc);
    float var  = sq * (1.f / Dc) - mean * mean;
    float rstd = rsqrtf(var + 1e-5f);
    __half2* orow = reinterpret_cast<__half2*>(out + (size_t)m * Dc);
#pragma unroll
    for (int j = 0; j < 4; j++) {
        int f4 = lane + 32 * j;
        float4 gv = reinterpret_cast<const float4*>(g)[f4];
        float4 bb = reinterpret_cast<const float4*>(be)[f4];
        float ox = (x4[j].x - mean) * rstd * gv.x + bb.x;
        float oy = (x4[j].y - mean) * rstd * gv.y + bb.y;
        float oz = (x4[j].z - mean) * rstd * gv.z + bb.z;
        float ow = (x4[j].w - mean) * rstd * gv.w + bb.w;
        orow[f4 * 2]     = __floats2half2_rn(ox, oy);
        orow[f4 * 2 + 1] = __floats2half2_rn(oz, ow);
    }
}

// ---------------- fp16 wmma GEMM (R12 proven): BM=128, BK=64, 3-stage ring ----------------
// EPI 0: merged QKV (N=1536) -> q/k/v head-major half
// EPI 1: Oproj -> outf[m*D+n] = v + bias + x_src(transposed gather)
// EPI 2: FFN1  -> outh[m*N+n] = half(gelu(v + bias))
// EPI 3: FFN2  -> outf[((b*T+t)*V+v)*D+n] = v + bias + resid[m*D+n]
constexpr int BM = 128, BN = 128, BKg = 64, NST = 3;
constexpr int ALDh = 72, BLDh = 136, SLDg = 136;
constexpr int ASTGh = BM * ALDh;          // 9216 halves / stage
constexpr int BSTGh = BKg * BLDh;         // 8704 halves / stage
constexpr size_t SMH = (size_t)NST * (ASTGh + BSTGh) * sizeof(__half);   // 107520 B

template <int EPI>
__global__ void __launch_bounds__(256, 2)
gemm_h(const __half* __restrict__ A, const __half* __restrict__ B,
       int M, int N, int K,
       const float* __restrict__ bias,
       const float* __restrict__ aux,
       float* __restrict__ outf, __half* __restrict__ outh,
       __half* __restrict__ outh2, __half* __restrict__ outh3)
{
    extern __shared__ char smraw[];
    __half* hbase = reinterpret_cast<__half*>(smraw);
    const int tid = threadIdx.x, wid = tid >> 5;
    const int wm = wid & 3, wn = wid >> 2;          // 4x2 warp grid, warp tile 32x64
    const int m0 = blockIdx.y * BM, n0 = blockIdx.x * BN;

    wmma::fragment<wmma::accumulator, 16, 16, 16, float> acc[2][4];
#pragma unroll
    for (int i = 0; i < 2; i++)
#pragma unroll
        for (int j = 0; j < 4; j++) wmma::fill_fragment(acc[i][j], 0.0f);

    auto load_stage = [&](int k0, int b) {
        __half* As = hbase + b * ASTGh;
        __half* Bs = hbase + NST * ASTGh + b * BSTGh;
#pragma unroll
        for (int i = 0; i < 4; i++) {               // A: 128x64 halves = 1024 x 16B
            int f = tid + 256 * i;
            int r = f >> 3, c = f & 7;
            cp_async16(As + r * ALDh + c * 8, A + (size_t)(m0 + r) * K + k0 + c * 8);
        }
#pragma unroll
        for (int i = 0; i < 4; i++) {               // B: 64x128 halves = 1024 x 16B
            int f = tid + 256 * i;
            int r = f >> 4, c = f & 15;
            cp_async16(Bs + r * BLDh + c * 8, B + (size_t)(k0 + r) * N + n0 + c * 8);
        }
    };

    const int nst = K / BKg;
    load_stage(0, 0); cp_commit();
    load_stage(BKg, 1); cp_commit();

    for (int s = 0; s < nst; s++) {
        if (s < nst - 1) cp_wait<1>(); else cp_wait<0>();
        __syncthreads();
        if (s + 2 < nst) { load_stage((s + 2) * BKg, (s + 2) % NST); cp_commit(); }

        const __half* As = hbase + (s % NST) * ASTGh;
        const __half* Bs = hbase + NST * ASTGh + (s % NST) * BSTGh;
#pragma unroll
        for (int kk = 0; kk < BKg; kk += 16) {
            wmma::fragment<wmma::matrix_a, 16, 16, 16, __half, wmma::row_major> af[2];
            wmma::fragment<wmma::matrix_b, 16, 16, 16, __half, wmma::row_major> bf[4];
#pragma unroll
            for (int i = 0; i < 2; i++)
                wmma::load_matrix_sync(af[i], As + (wm * 32 + i * 16) * ALDh + kk, ALDh);
#pragma unroll
            for (int j = 0; j < 4; j++)
                wmma::load_matrix_sync(bf[j], Bs + kk * BLDh + wn * 64 + j * 16, BLDh);
#pragma unroll
            for (int i = 0; i < 2; i++)
#pragma unroll
                for (int j = 0; j < 4; j++)
                    wmma::mma_sync(acc[i][j], af[i], bf[j], acc[i][j]);
        }
    }
    __syncthreads();   // drain before reusing smem as fp32 staging

    float* St = reinterpret_cast<float*>(smraw);    // [128][136]
#pragma unroll
    for (int i = 0; i < 2; i++)
#pragma unroll
        for (int j = 0; j < 4; j++)
            wmma::store_matrix_sync(St + (wm * 32 + i * 16) * SLDg + wn * 64 + j * 16,
                                    acc[i][j], SLDg, wmma::mem_row_major);
    __syncthreads();

    for (int idx = tid; idx < BM * BN; idx += 256) {
        int r = idx >> 7, c = idx & 127;
        float v = St[r * SLDg + c];
        int gm = m0 + r, gn = n0 + c;
        v += bias[gn];
        if (EPI == 0) {
            int bv = gm >> 9, t = gm & 511;
            int which = gn >> 9, n = gn & 511, h = n >> 6, dh = n & 63;
            __half* dst = (which == 0) ? outh : (which == 1) ? outh2 : outh3;
            dst[(((size_t)(bv * Hc + h) * Tc + t) << 6) + dh] = __float2half(v);
        } else if (EPI == 1) {
            int bv = gm >> 9, t = gm & 511, b2 = bv / Vc, vv = bv % Vc;
            v += aux[((size_t)((b2 * Tc + t) * Vc + vv) << 9) + gn];
            outf[((size_t)gm << 9) + gn] = v;
        } else if (EPI == 2) {
            v = 0.5f * v * (1.0f + erff(v * 0.70710678118654752f));
            outh[(size_t)gm * N + gn] = __float2half(v);
        } else {
            int bv = gm >> 9, t = gm & 511, b2 = bv / Vc, vv = bv % Vc;
            v += aux[((size_t)gm << 9) + gn];
            outf[((size_t)((b2 * Tc + t) * Vc + vv) << 9) + gn] = v;
        }
    }
}

// ---------------- Attention v3: QB=64, half scores, 128-row K/V chunks ----------------
// Block = (bv, h, 64-query tile). 8 warps. Phase A accumulates UNSCALED scores
// in fp16 wmma accumulators, stores half; softmax applies 1/8 scale + mask in
// fp32; probs written back as half; Phase B fp32 accumulate. 2 CTAs/SM.
constexpr int QB = 64, CK = 128, KLDh = 72, SLDh = 520;   // SLDh in halves
constexpr int OS_Q  = (QB * SLDh) / 2;                 // 16640 floats (scores = 66560 B)
constexpr int OS_KV = OS_Q + (QB * KLDh) / 2;          // 18944
constexpr int OS_MB = OS_KV + (2 * CK * KLDh) / 2;     // 28160
constexpr size_t SMA = (size_t)(OS_MB + Tc) * sizeof(float);   // 114688 B

__global__ void __launch_bounds__(256, 2)
attn_kernel(const __half* __restrict__ Q, const __half* __restrict__ K,
            const __half* __restrict__ V, const int* __restrict__ mask,
            __half* __restrict__ out)
{
    extern __shared__ float f[];
    __half* hp  = reinterpret_cast<__half*>(f);          // scores/probs, [64][520] half
    __half* hq  = reinterpret_cast<__half*>(f + OS_Q);   // Q tile [64][72] half
    __half* hkv = reinterpret_cast<__half*>(f + OS_KV);  // 2 x [128][72] half
    const int tid = threadIdx.x, wid = tid >> 5, lane = tid & 31;
    const int q0 = blockIdx.x * QB, h = blockIdx.y, bv = blockIdx.z, b = bv / Vc;
    const __half* Qh = Q + (size_t)(bv * Hc + h) * Tc * DHc;
    const __half* Kh = K + (size_t)(bv * Hc + h) * Tc * DHc;
    const __half* Vh = V + (size_t)(bv * Hc + h) * Tc * DHc;
    const int tm = wid & 3, tn = wid >> 2;   // 4x2 warp grid

    // Q tile: 64x64 halves = 512 x 16B; K chunk 0: 128x64 halves = 1024 x 16B
#pragma unroll
    for (int i = 0; i < 2; i++) {
        int fi = tid + 256 * i; int r = fi >> 3, c = fi & 7;
        cp_async16(hq + r * KLDh + c * 8, Qh + (size_t)(q0 + r) * DHc + c * 8);
    }
#pragma unroll
    for (int i = 0; i < 4; i++) {
        int fi = tid + 256 * i; int r = fi >> 3, c = fi & 7;
        cp_async16(hkv + r * KLDh + c * 8, Kh + (size_t)r * DHc + c * 8);
    }
    cp_commit();
    for (int j = tid; j < Tc; j += 256)
        f[OS_MB + j] = (mask[(size_t)b * Tc + j] != 0) ? 0.f : -INFINITY;

    // ---- Phase A: S = Q K^T (unscaled), 4 chunks of 128 keys ----
    // warp (tm, tn): rows [tm*16, +16), cols [tn*64, +64) of each 64x128 chunk tile
    for (int c = 0; c < 4; c++) {
        if (c + 1 < 4) {
            const __half* src = Kh + (size_t)(c + 1) * CK * DHc;
            __half* dst = hkv + ((c + 1) & 1) * (CK * KLDh);
#pragma unroll
            for (int i = 0; i < 4; i++) {
                int fi = tid + 256 * i; int r = fi >> 3, cc = fi & 7;
                cp_async16(dst + r * KLDh + cc * 8, src + (size_t)r * DHc + cc * 8);
            }
            cp_commit();
            cp_wait<1>();
        } else cp_wait<0>();
        __syncthreads();

        const __half* kb = hkv + (c & 1) * (CK * KLDh);
        wmma::fragment<wmma::accumulator, 16, 16, 16, __half> accA[4];
#pragma unroll
        for (int s2 = 0; s2 < 4; s2++) wmma::fill_fragment(accA[s2], __float2half(0.f));
#pragma unroll
        for (int kk = 0; kk < DHc; kk += 16) {
            wmma::fragment<wmma::matrix_a, 16, 16, 16, __half, wmma::row_major> af;
            wmma::load_matrix_sync(af, hq + (tm * 16) * KLDh + kk, KLDh);
#pragma unroll
            for (int s2 = 0; s2 < 4; s2++) {
                wmma::fragment<wmma::matrix_b, 16, 16, 16, __half, wmma::col_major> bf;
                wmma::load_matrix_sync(bf, kb + (tn * 64 + s2 * 16) * KLDh + kk, KLDh);
                wmma::mma_sync(accA[s2], af, bf, accA[s2]);
            }
        }
#pragma unroll
        for (int s2 = 0; s2 < 4; s2++)
            wmma::store_matrix_sync(hp + (size_t)(tm * 16) * SLDh + c * 128 + tn * 64 + s2 * 16,
                                    accA[s2], SLDh, wmma::mem_row_major);
        __syncthreads();   // protect KV buffer reuse by next iteration's loads
    }

    // prefetch V chunk 0 under softmax (buf0 free after last sync)
#pragma unroll
    for (int i = 0; i < 4; i++) {
        int fi = tid + 256 * i; int r = fi >> 3, cc = fi & 7;
        cp_async16(hkv + r * KLDh + cc * 8, Vh + (size_t)r * DHc + cc * 8);
    }
    cp_commit();

    // ---- softmax: each warp owns 8 rows; scale 1/8 + mask bias in fp32 ----
#pragma unroll
    for (int rr = 0; rr < 8; rr++) {
        int row = wid * 8 + rr;
        __half* hrow = hp + (size_t)row * SLDh;
        float vv[16];
        float mx = -INFINITY;
#pragma unroll
        for (int jj = 0; jj < 16; jj++) {
            int j = lane + 32 * jj;
            vv[jj] = __half2float(hrow[j]) * 0.125f + f[OS_MB + j];
            mx = fmaxf(mx, vv[jj]);
        }
#pragma unroll
        for (int o = 16; o > 0; o >>= 1) mx = fmaxf(mx, __shfl_xor_sync(0xffffffffu, mx, o));
        float sum = 0.f;
#pragma unroll
        for (int jj = 0; jj < 16; jj++) { vv[jj] = __expf(vv[jj] - mx); sum += vv[jj]; }
#pragma unroll
        for (int o = 16; o > 0; o >>= 1) sum += __shfl_xor_sync(0xffffffffu, sum, o);
        float inv = 1.f / sum;
#pragma unroll
        for (int jj = 0; jj < 16; jj++) hrow[lane + 32 * jj] = __float2half(vv[jj] * inv);
    }
    __syncthreads();

    // ---- Phase B: O = P V, 4 chunks of 128 keys ----
    // warp (tm, tn): rows [tm*16, +16), cols [tn*32, +32): 2 fp32 accumulators
    wmma::fragment<wmma::accumulator, 16, 16, 16, float> accO[2];
#pragma unroll
    for (int j = 0; j < 2; j++) wmma::fill_fragment(accO[j], 0.0f);
    for (int c = 0; c < 4; c++) {
        if (c + 1 < 4) {
            const __half* src = Vh + (size_t)(c + 1) * CK * DHc;
            __half* dst = hkv + ((c + 1) & 1) * (CK * KLDh);
#pragma unroll
            for (int i = 0; i < 4; i++) {
                int fi = tid + 256 * i; int r = fi >> 3, cc = fi & 7;
                cp_async16(dst + r * KLDh + cc * 8, src + (size_t)r * DHc + cc * 8);
            }
            cp_commit();
            cp_wait<1>();
        } else cp_wait<0>();
        __syncthreads();

        const __half* vb = hkv + (c & 1) * (CK * KLDh);
#pragma unroll
        for (int kk = 0; kk < CK; kk += 16) {
            wmma::fragment<wmma::matrix_a, 16, 16, 16, __half, wmma::row_major> af;
            wmma::load_matrix_sync(af, hp + (size_t)(tm * 16) * SLDh + c * 128 + kk, SLDh);
#pragma unroll
            for (int j = 0; j < 2; j++) {
                wmma::fragment<wmma::matrix_b, 16, 16, 16, __half, wmma::row_major> bf;
                wmma::load_matrix_sync(bf, vb + kk * KLDh + tn * 32 + j * 16, KLDh);
                wmma::mma_sync(accO[j], af, bf, accO[j]);
            }
        }
        __syncthreads();   // protect KV buffer reuse (and probs before staging)
    }

    // stage 64x64 fp32 result over the (now dead) scores region, then half store
    float* St2 = f;          // [64][68] = 17408 floats <= scores region
#pragma unroll
    for (int j = 0; j < 2; j++)
        wmma::store_matrix_sync(St2 + (tm * 16) * 68 + tn * 32 + j * 16, accO[j],
                                68, wmma::mem_row_major);
    __syncthreads();
    for (int idx = tid; idx < QB * 64; idx += 256) {
        int r = idx >> 6, c = idx & 63;
        out[(size_t)(bv * Tc + q0 + r) * Dc + h * DHc + c] = __float2half(St2[r * 68 + c]);
    }
}

// ---------------- launch ----------------
extern "C" void kernel_launch(void* const* d_in, const int* in_sizes, int n_in,
                              void* d_out, int out_size)
{
    const float* x  = (const float*)d_in[0];
    const int* mask = (const int*)d_in[1];          // bool -> int32 in harness
    const float* Wq = (const float*)d_in[2];
    const float* bq = (const float*)d_in[3];
    const float* Wk = (const float*)d_in[4];
    const float* bk = (const float*)d_in[5];
    const float* Wv = (const float*)d_in[6];
    const float* bvb = (const float*)d_in[7];
    const float* Wo = (const float*)d_in[8];
    const float* bo = (const float*)d_in[9];
    const float* W1 = (const float*)d_in[10];
    const float* b1 = (const float*)d_in[11];
    const float* W2 = (const float*)d_in[12];
    const float* b2 = (const float*)d_in[13];
    const float* g1 = (const float*)d_in[14];
    const float* be1 = (const float*)d_in[15];
    const float* g2 = (const float*)d_in[16];
    const float* be2 = (const float*)d_in[17];
    float* out = (float*)d_out;

    __half *xnh, *qh, *kh, *vh, *ath, *h2h, *ffh, *wqkv, *who, *wh1, *wh2;
    float *xr, *bqkv;
    cudaGetSymbolAddress((void**)&xnh,  g_xnh);
    cudaGetSymbolAddress((void**)&qh,   g_qh);
    cudaGetSymbolAddress((void**)&kh,   g_kh);
    cudaGetSymbolAddress((void**)&vh,   g_vh);
    cudaGetSymbolAddress((void**)&ath,  g_ath);
    cudaGetSymbolAddress((void**)&h2h,  g_h2h);
    cudaGetSymbolAddress((void**)&ffh,  g_ffh);
    cudaGetSymbolAddress((void**)&xr,   g_xr);
    cudaGetSymbolAddress((void**)&wqkv, g_wqkv);
    cudaGetSymbolAddress((void**)&bqkv, g_bqkv);
    cudaGetSymbolAddress((void**)&who,  g_who);
    cudaGetSymbolAddress((void**)&wh1,  g_wh1);
    cudaGetSymbolAddress((void**)&wh2,  g_wh2);

    cudaFuncSetAttribute(gemm_h<0>, cudaFuncAttributeMaxDynamicSharedMemorySize, (int)SMH);
    cudaFuncSetAttribute(gemm_h<1>, cudaFuncAttributeMaxDynamicSharedMemorySize, (int)SMH);
    cudaFuncSetAttribute(gemm_h<2>, cudaFuncAttributeMaxDynamicSharedMemorySize, (int)SMH);
    cudaFuncSetAttribute(gemm_h<3>, cudaFuncAttributeMaxDynamicSharedMemorySize, (int)SMH);
    cudaFuncSetAttribute(attn_kernel, cudaFuncAttributeMaxDynamicSharedMemorySize, (int)SMA);

    // 0. weights fp32 -> fp16 (QKV concatenated into [512][1536])
    wconv_off<<<Dc * Dc / 4 / 256, 256>>>(Wq, wqkv, 0);
    wconv_off<<<Dc * Dc / 4 / 256, 256>>>(Wk, wqkv, Dc);
    wconv_off<<<Dc * Dc / 4 / 256, 256>>>(Wv, wqkv, 2 * Dc);
    bcat<<<2, 256>>>(bq, bk, bvb, bqkv);
    wconv<<<Dc * Dc / 4 / 256, 256>>>(Wo, who, Dc * Dc / 4);
    wconv<<<Dc * DFFc / 4 / 256, 256>>>(W1, wh1, Dc * DFFc / 4);
    wconv<<<DFFc * Dc / 4 / 256, 256>>>(W2, wh2, DFFc * Dc / 4);

    dim3 gqkv(3 * Dc / BN, MTOK / BM);   // (12, 768)
    dim3 g512(Dc / BN, MTOK / BM);       // (4, 768)
    dim3 gff(DFFc / BN, MTOK / BM);      // (16, 768)

    // 1. LN1 (gather-transpose from x) -> half
    ln_kernel<<<MTOK / 8, 256>>>(x, g1, be1, xnh, 1);
    // 2. merged QKV projection -> head-major half
    gemm_h<0><<<gqkv, 256, SMH>>>(xnh, wqkv, MTOK, 3 * Dc, Dc, bqkv, nullptr,
                                  nullptr, qh, kh, vh);
    // 3. Attention -> half (QB=64 tiles)
    attn_kernel<<<dim3(Tc / QB, Hc, BV), 256, SMA>>>(qh, kh, vh, mask, ath);
    // 4. O-projection + residual (x gathered) -> xr fp32
    gemm_h<1><<<g512, 256, SMH>>>(ath, who, MTOK, Dc, Dc, bo, x, xr, nullptr,
                                  nullptr, nullptr);
    // 5. LN2 -> half
    ln_kernel<<<MTOK / 8, 256>>>(xr, g2, be2, h2h, 0);
    // 6. FFN1 + bias + exact gelu -> half
    gemm_h<2><<<gff, 256, SMH>>>(h2h, wh1, MTOK, DFFc, Dc, b1, nullptr,
                                 nullptr, ffh, nullptr, nullptr);
    // 7. FFN2 + bias + residual + scatter-transpose -> fp32 d_out
    gemm_h<3><<<g512, 256, SMH>>>(ffh, wh2, MTOK, Dc, DFFc, b2, xr, out,
                                  nullptr, nullptr, nullptr);
}

// round 17
// speedup vs baseline: 1.3675x; 1.0548x over previous
#include <cuda_runtime.h>
#include <cuda_fp16.h>
#include <mma.h>
#include <cstdint>
#include <cstddef>

using namespace nvcuda;

// Problem constants
constexpr int Bc = 8, Tc = 512, Vc = 24, Dc = 512, Hc = 8, DHc = 64, DFFc = 2048;
constexpr int BV = Bc * Vc;              // 192
constexpr int MTOK = BV * Tc;            // 98304 tokens

// ---------------- scratch (device globals; allocation-free rule) ----------------
__device__ __half g_xnh [(size_t)MTOK * Dc];    // LN1 out (half)
__device__ __half g_qh  [(size_t)MTOK * Dc];    // Q head-major (half)
__device__ __half g_kh  [(size_t)MTOK * Dc];
__device__ __half g_vh  [(size_t)MTOK * Dc];
__device__ __half g_ath [(size_t)MTOK * Dc];    // attention out (half)
__device__ __half g_h2h [(size_t)MTOK * Dc];    // LN2 out (half)
__device__ __half g_ffh [(size_t)MTOK * DFFc];  // FFN hidden (half)
__device__ float  g_xr  [(size_t)MTOK * Dc];    // residual stream (fp32)
// half weights
__device__ __half g_wqkv[Dc * 3 * Dc];          // [K=512][N=1536] concat Q|K|V
__device__ float  g_bqkv[3 * Dc];               // concat biases
__device__ __half g_who[Dc * Dc];
__device__ __half g_wh1[Dc * DFFc];
__device__ __half g_wh2[DFFc * Dc];

// ---------------- helpers ----------------
__device__ __forceinline__ void cp_async16(void* smem, const void* g) {
    uint32_t s = (uint32_t)__cvta_generic_to_shared(smem);
    asm volatile("cp.async.cg.shared.global [%0], [%1], 16;\n" :: "r"(s), "l"(g));
}
__device__ __forceinline__ void cp_commit() { asm volatile("cp.async.commit_group;\n"); }
template <int N>
__device__ __forceinline__ void cp_wait() { asm volatile("cp.async.wait_group %0;\n" :: "n"(N)); }

__device__ __forceinline__ uint2 pack_half4(float a, float b, float c, float d) {
    uint2 r;
    __half2 lo = __floats2half2_rn(a, b), hi = __floats2half2_rn(c, d);
    r.x = *reinterpret_cast<uint32_t*>(&lo);
    r.y = *reinterpret_cast<uint32_t*>(&hi);
    return r;
}

// ---------------- weight prep (2 launches total) ----------------
// Launch 1: QKV weights -> concat [512][1536] half, plus bias concat.
__global__ void wprep_qkv(const float* __restrict__ Wq, const float* __restrict__ Wk,
                          const float* __restrict__ Wv,
                          const float* __restrict__ bq, const float* __restrict__ bk,
                          const float* __restrict__ bv,
                          __half* __restrict__ wqkv, float* __restrict__ bqkv)
{
    int i = blockIdx.x * 256 + threadIdx.x;          // over 3 * 512*512/4 = 196608
    const int per = Dc * Dc / 4;
    int which = i / per, rem = i - which * per;
    const float* src = (which == 0) ? Wq : (which == 1) ? Wk : Wv;
    int k = (rem * 4) >> 9, n = (rem * 4) & 511;
    float4 v = reinterpret_cast<const float4*>(src)[rem];
    __half2* o = reinterpret_cast<__half2*>(wqkv + (size_t)k * (3 * Dc) + which * Dc + n);
    o[0] = __floats2half2_rn(v.x, v.y);
    o[1] = __floats2half2_rn(v.z, v.w);
    if (i < Dc) { bqkv[i] = bq[i]; bqkv[Dc + i] = bk[i]; bqkv[2 * Dc + i] = bv[i]; }
}
// Launch 2: Wo, W1, W2 -> half.
__global__ void wprep_rest(const float* __restrict__ Wo, const float* __restrict__ W1,
                           const float* __restrict__ W2,
                           __half* __restrict__ who, __half* __restrict__ wh1,
                           __half* __restrict__ wh2)
{
    int i = blockIdx.x * 256 + threadIdx.x;
    const int n_o = Dc * Dc / 4, n_1 = Dc * DFFc / 4, n_2 = DFFc * Dc / 4;
    const float* src; __half* dst; int rem;
    if (i < n_o)            { src = Wo; dst = who; rem = i; }
    else if (i < n_o + n_1) { src = W1; dst = wh1; rem = i - n_o; }
    else if (i < n_o + n_1 + n_2) { src = W2; dst = wh2; rem = i - n_o - n_1; }
    else return;
    float4 v = reinterpret_cast<const float4*>(src)[rem];
    reinterpret_cast<__half2*>(dst)[rem * 2]     = __floats2half2_rn(v.x, v.y);
    reinterpret_cast<__half2*>(dst)[rem * 2 + 1] = __floats2half2_rn(v.z, v.w);
}

// ---------------- LayerNorm: one warp per token, half output ----------------
__global__ void ln_kernel(const float* __restrict__ in, const float* __restrict__ g,
                          const float* __restrict__ be, __half* __restrict__ out, int trans)
{
    int tid = threadIdx.x, wid = tid >> 5, lane = tid & 31;
    int m = blockIdx.x * 8 + wid;
    const float* row;
    if (trans) {
        int bv = m >> 9, t = m & 511;
        int b = bv / Vc, v = bv % Vc;
        row = in + ((size_t)((b * Tc + t) * Vc + v)) * Dc;
    } else {
        row = in + (size_t)m * Dc;
    }
    float4 x4[4];
    float sum = 0.f, sq = 0.f;
#pragma unroll
    for (int j = 0; j < 4; j++) {
        x4[j] = reinterpret_cast<const float4*>(row)[lane + 32 * j];
        sum += x4[j].x + x4[j].y + x4[j].z + x4[j].w;
        sq  += x4[j].x * x4[j].x + x4[j].y * x4[j].y + x4[j].z * x4[j].z + x4[j].w * x4[j].w;
    }
#pragma unroll
    for (int o = 16; o > 0; o >>= 1) {
        sum += __shfl_xor_sync(0xffffffffu, sum, o);
        sq  += __shfl_xor_sync(0xffffffffu, sq,  o);
    }
    float mean = sum * (1.f / Dc);
    float var  = sq * (1.f / Dc) - mean * mean;
    float rstd = rsqrtf(var + 1e-5f);
    __half2* orow = reinterpret_cast<__half2*>(out + (size_t)m * Dc);
#pragma unroll
    for (int j = 0; j < 4; j++) {
        int f4 = lane + 32 * j;
        float4 gv = reinterpret_cast<const float4*>(g)[f4];
        float4 bb = reinterpret_cast<const float4*>(be)[f4];
        float ox = (x4[j].x - mean) * rstd * gv.x + bb.x;
        float oy = (x4[j].y - mean) * rstd * gv.y + bb.y;
        float oz = (x4[j].z - mean) * rstd * gv.z + bb.z;
        float ow = (x4[j].w - mean) * rstd * gv.w + bb.w;
        orow[f4 * 2]     = __floats2half2_rn(ox, oy);
        orow[f4 * 2 + 1] = __floats2half2_rn(oz, ow);
    }
}

// ---------------- fp16 wmma GEMM (R12 core): BM=128, BK=64, 3-stage ring ----------------
// Vectorized epilogues (float4 smem reads, 8B/16B global stores).
// EPI 0: merged QKV (N=1536) -> q/k/v head-major half
// EPI 1: Oproj -> outf[m*D+n] = v + bias + x_src(transposed gather)
// EPI 2: FFN1  -> outh[m*N+n] = half(gelu(v + bias))
// EPI 3: FFN2  -> outf[((b*T+t)*V+v)*D+n] = v + bias + resid[m*D+n]
constexpr int BM = 128, BN = 128, BKg = 64, NST = 3;
constexpr int ALDh = 72, BLDh = 136, SLDg = 136;
constexpr int ASTGh = BM * ALDh;          // 9216 halves / stage
constexpr int BSTGh = BKg * BLDh;         // 8704 halves / stage
constexpr size_t SMH = (size_t)NST * (ASTGh + BSTGh) * sizeof(__half);   // 107520 B

template <int EPI>
__global__ void __launch_bounds__(256, 2)
gemm_h(const __half* __restrict__ A, const __half* __restrict__ B,
       int M, int N, int K,
       const float* __restrict__ bias,
       const float* __restrict__ aux,
       float* __restrict__ outf, __half* __restrict__ outh,
       __half* __restrict__ outh2, __half* __restrict__ outh3)
{
    extern __shared__ char smraw[];
    __half* hbase = reinterpret_cast<__half*>(smraw);
    const int tid = threadIdx.x, wid = tid >> 5;
    const int wm = wid & 3, wn = wid >> 2;          // 4x2 warp grid, warp tile 32x64
    const int m0 = blockIdx.y * BM, n0 = blockIdx.x * BN;

    wmma::fragment<wmma::accumulator, 16, 16, 16, float> acc[2][4];
#pragma unroll
    for (int i = 0; i < 2; i++)
#pragma unroll
        for (int j = 0; j < 4; j++) wmma::fill_fragment(acc[i][j], 0.0f);

    auto load_stage = [&](int k0, int b) {
        __half* As = hbase + b * ASTGh;
        __half* Bs = hbase + NST * ASTGh + b * BSTGh;
#pragma unroll
        for (int i = 0; i < 4; i++) {               // A: 128x64 halves = 1024 x 16B
            int f = tid + 256 * i;
            int r = f >> 3, c = f & 7;
            cp_async16(As + r * ALDh + c * 8, A + (size_t)(m0 + r) * K + k0 + c * 8);
        }
#pragma unroll
        for (int i = 0; i < 4; i++) {               // B: 64x128 halves = 1024 x 16B
            int f = tid + 256 * i;
            int r = f >> 4, c = f & 15;
            cp_async16(Bs + r * BLDh + c * 8, B + (size_t)(k0 + r) * N + n0 + c * 8);
        }
    };

    const int nst = K / BKg;
    load_stage(0, 0); cp_commit();
    load_stage(BKg, 1); cp_commit();

    for (int s = 0; s < nst; s++) {
        if (s < nst - 1) cp_wait<1>(); else cp_wait<0>();
        __syncthreads();
        if (s + 2 < nst) { load_stage((s + 2) * BKg, (s + 2) % NST); cp_commit(); }

        const __half* As = hbase + (s % NST) * ASTGh;
        const __half* Bs = hbase + NST * ASTGh + (s % NST) * BSTGh;
#pragma unroll
        for (int kk = 0; kk < BKg; kk += 16) {
            wmma::fragment<wmma::matrix_a, 16, 16, 16, __half, wmma::row_major> af[2];
            wmma::fragment<wmma::matrix_b, 16, 16, 16, __half, wmma::row_major> bf[4];
#pragma unroll
            for (int i = 0; i < 2; i++)
                wmma::load_matrix_sync(af[i], As + (wm * 32 + i * 16) * ALDh + kk, ALDh);
#pragma unroll
            for (int j = 0; j < 4; j++)
                wmma::load_matrix_sync(bf[j], Bs + kk * BLDh + wn * 64 + j * 16, BLDh);
#pragma unroll
            for (int i = 0; i < 2; i++)
#pragma unroll
                for (int j = 0; j < 4; j++)
                    wmma::mma_sync(acc[i][j], af[i], bf[j], acc[i][j]);
        }
    }
    __syncthreads();   // drain before reusing smem as fp32 staging

    float* St = reinterpret_cast<float*>(smraw);    // [128][136]
#pragma unroll
    for (int i = 0; i < 2; i++)
#pragma unroll
        for (int j = 0; j < 4; j++)
            wmma::store_matrix_sync(St + (wm * 32 + i * 16) * SLDg + wn * 64 + j * 16,
                                    acc[i][j], SLDg, wmma::mem_row_major);
    __syncthreads();

    // vectorized epilogue: each iteration handles 4 contiguous columns
    for (int idx = tid; idx < BM * BN / 4; idx += 256) {
        int r = idx >> 5, c = (idx & 31) * 4;
        float4 v = *reinterpret_cast<const float4*>(St + r * SLDg + c);
        int gm = m0 + r, gn = n0 + c;
        float4 bv4 = *reinterpret_cast<const float4*>(bias + gn);
        v.x += bv4.x; v.y += bv4.y; v.z += bv4.z; v.w += bv4.w;
        if (EPI == 0) {
            // 4 cols stay inside one 64-wide head (4 | 64)
            int bv = gm >> 9, t = gm & 511;
            int which = gn >> 9, n = gn & 511, h = n >> 6, dh = n & 63;
            __half* dst = (which == 0) ? outh : (which == 1) ? outh2 : outh3;
            *reinterpret_cast<uint2*>(dst + (((size_t)(bv * Hc + h) * Tc + t) << 6) + dh) =
                pack_half4(v.x, v.y, v.z, v.w);
        } else if (EPI == 1) {
            int bv = gm >> 9, t = gm & 511, b2 = bv / Vc, vv = bv % Vc;
            float4 a4 = *reinterpret_cast<const float4*>(
                aux + ((size_t)((b2 * Tc + t) * Vc + vv) << 9) + gn);
            v.x += a4.x; v.y += a4.y; v.z += a4.z; v.w += a4.w;
            *reinterpret_cast<float4*>(outf + ((size_t)gm << 9) + gn) = v;
        } else if (EPI == 2) {
            v.x = 0.5f * v.x * (1.0f + erff(v.x * 0.70710678118654752f));
            v.y = 0.5f * v.y * (1.0f + erff(v.y * 0.70710678118654752f));
            v.z = 0.5f * v.z * (1.0f + erff(v.z * 0.70710678118654752f));
            v.w = 0.5f * v.w * (1.0f + erff(v.w * 0.70710678118654752f));
            *reinterpret_cast<uint2*>(outh + (size_t)gm * N + gn) =
                pack_half4(v.x, v.y, v.z, v.w);
        } else {
            int bv = gm >> 9, t = gm & 511, b2 = bv / Vc, vv = bv % Vc;
            float4 a4 = *reinterpret_cast<const float4*>(aux + ((size_t)gm << 9) + gn);
            v.x += a4.x; v.y += a4.y; v.z += a4.z; v.w += a4.w;
            *reinterpret_cast<float4*>(
                outf + ((size_t)((b2 * Tc + t) * Vc + vv) << 9) + gn) = v;
        }
    }
}

// ---------------- Attention v3 (R16 proven): QB=64, half scores ----------------
constexpr int QB = 64, CK = 128, KLDh = 72, SLDh = 520;   // SLDh in halves
constexpr int OS_Q  = (QB * SLDh) / 2;                 // 16640 floats (scores = 66560 B)
constexpr int OS_KV = OS_Q + (QB * KLDh) / 2;          // 18944
constexpr int OS_MB = OS_KV + (2 * CK * KLDh) / 2;     // 28160
constexpr size_t SMA = (size_t)(OS_MB + Tc) * sizeof(float);   // 114688 B

__global__ void __launch_bounds__(256, 2)
attn_kernel(const __half* __restrict__ Q, const __half* __restrict__ K,
            const __half* __restrict__ V, const int* __restrict__ mask,
            __half* __restrict__ out)
{
    extern __shared__ float f[];
    __half* hp  = reinterpret_cast<__half*>(f);          // scores/probs, [64][520] half
    __half* hq  = reinterpret_cast<__half*>(f + OS_Q);   // Q tile [64][72] half
    __half* hkv = reinterpret_cast<__half*>(f + OS_KV);  // 2 x [128][72] half
    const int tid = threadIdx.x, wid = tid >> 5, lane = tid & 31;
    const int q0 = blockIdx.x * QB, h = blockIdx.y, bv = blockIdx.z, b = bv / Vc;
    const __half* Qh = Q + (size_t)(bv * Hc + h) * Tc * DHc;
    const __half* Kh = K + (size_t)(bv * Hc + h) * Tc * DHc;
    const __half* Vh = V + (size_t)(bv * Hc + h) * Tc * DHc;
    const int tm = wid & 3, tn = wid >> 2;   // 4x2 warp grid

#pragma unroll
    for (int i = 0; i < 2; i++) {
        int fi = tid + 256 * i; int r = fi >> 3, c = fi & 7;
        cp_async16(hq + r * KLDh + c * 8, Qh + (size_t)(q0 + r) * DHc + c * 8);
    }
#pragma unroll
    for (int i = 0; i < 4; i++) {
        int fi = tid + 256 * i; int r = fi >> 3, c = fi & 7;
        cp_async16(hkv + r * KLDh + c * 8, Kh + (size_t)r * DHc + c * 8);
    }
    cp_commit();
    for (int j = tid; j < Tc; j += 256)
        f[OS_MB + j] = (mask[(size_t)b * Tc + j] != 0) ? 0.f : -INFINITY;

    // ---- Phase A: S = Q K^T (unscaled, fp16 accum), 4 chunks of 128 keys ----
    for (int c = 0; c < 4; c++) {
        if (c + 1 < 4) {
            const __half* src = Kh + (size_t)(c + 1) * CK * DHc;
            __half* dst = hkv + ((c + 1) & 1) * (CK * KLDh);
#pragma unroll
            for (int i = 0; i < 4; i++) {
                int fi = tid + 256 * i; int r = fi >> 3, cc = fi & 7;
                cp_async16(dst + r * KLDh + cc * 8, src + (size_t)r * DHc + cc * 8);
            }
            cp_commit();
            cp_wait<1>();
        } else cp_wait<0>();
        __syncthreads();

        const __half* kb = hkv + (c & 1) * (CK * KLDh);
        wmma::fragment<wmma::accumulator, 16, 16, 16, __half> accA[4];
#pragma unroll
        for (int s2 = 0; s2 < 4; s2++) wmma::fill_fragment(accA[s2], __float2half(0.f));
#pragma unroll
        for (int kk = 0; kk < DHc; kk += 16) {
            wmma::fragment<wmma::matrix_a, 16, 16, 16, __half, wmma::row_major> af;
            wmma::load_matrix_sync(af, hq + (tm * 16) * KLDh + kk, KLDh);
#pragma unroll
            for (int s2 = 0; s2 < 4; s2++) {
                wmma::fragment<wmma::matrix_b, 16, 16, 16, __half, wmma::col_major> bf;
                wmma::load_matrix_sync(bf, kb + (tn * 64 + s2 * 16) * KLDh + kk, KLDh);
                wmma::mma_sync(accA[s2], af, bf, accA[s2]);
            }
        }
#pragma unroll
        for (int s2 = 0; s2 < 4; s2++)
            wmma::store_matrix_sync(hp + (size_t)(tm * 16) * SLDh + c * 128 + tn * 64 + s2 * 16,
                                    accA[s2], SLDh, wmma::mem_row_major);
        __syncthreads();   // protect KV buffer reuse by next iteration's loads
    }

    // prefetch V chunk 0 under softmax
#pragma unroll
    for (int i = 0; i < 4; i++) {
        int fi = tid + 256 * i; int r = fi >> 3, cc = fi & 7;
        cp_async16(hkv + r * KLDh + cc * 8, Vh + (size_t)r * DHc + cc * 8);
    }
    cp_commit();

    // ---- softmax: each warp owns 8 rows; scale 1/8 + mask bias in fp32 ----
#pragma unroll
    for (int rr = 0; rr < 8; rr++) {
        int row = wid * 8 + rr;
        __half* hrow = hp + (size_t)row * SLDh;
        float vv[16];
        float mx = -INFINITY;
#pragma unroll
        for (int jj = 0; jj < 16; jj++) {
            int j = lane + 32 * jj;
            vv[jj] = __half2float(hrow[j]) * 0.125f + f[OS_MB + j];
            mx = fmaxf(mx, vv[jj]);
        }
#pragma unroll
        for (int o = 16; o > 0; o >>= 1) mx = fmaxf(mx, __shfl_xor_sync(0xffffffffu, mx, o));
        float sum = 0.f;
#pragma unroll
        for (int jj = 0; jj < 16; jj++) { vv[jj] = __expf(vv[jj] - mx); sum += vv[jj]; }
#pragma unroll
        for (int o = 16; o > 0; o >>= 1) sum += __shfl_xor_sync(0xffffffffu, sum, o);
        float inv = 1.f / sum;
#pragma unroll
        for (int jj = 0; jj < 16; jj++) hrow[lane + 32 * jj] = __float2half(vv[jj] * inv);
    }
    __syncthreads();

    // ---- Phase B: O = P V (fp32 accum), 4 chunks of 128 keys ----
    wmma::fragment<wmma::accumulator, 16, 16, 16, float> accO[2];
#pragma unroll
    for (int j = 0; j < 2; j++) wmma::fill_fragment(accO[j], 0.0f);
    for (int c = 0; c < 4; c++) {
        if (c + 1 < 4) {
            const __half* src = Vh + (size_t)(c + 1) * CK * DHc;
            __half* dst = hkv + ((c + 1) & 1) * (CK * KLDh);
#pragma unroll
            for (int i = 0; i < 4; i++) {
                int fi = tid + 256 * i; int r = fi >> 3, cc = fi & 7;
                cp_async16(dst + r * KLDh + cc * 8, src + (size_t)r * DHc + cc * 8);
            }
            cp_commit();
            cp_wait<1>();
        } else cp_wait<0>();
        __syncthreads();

        const __half* vb = hkv + (c & 1) * (CK * KLDh);
#pragma unroll
        for (int kk = 0; kk < CK; kk += 16) {
            wmma::fragment<wmma::matrix_a, 16, 16, 16, __half, wmma::row_major> af;
            wmma::load_matrix_sync(af, hp + (size_t)(tm * 16) * SLDh + c * 128 + kk, SLDh);
#pragma unroll
            for (int j = 0; j < 2; j++) {
                wmma::fragment<wmma::matrix_b, 16, 16, 16, __half, wmma::row_major> bf;
                wmma::load_matrix_sync(bf, vb + kk * KLDh + tn * 32 + j * 16, KLDh);
                wmma::mma_sync(accO[j], af, bf, accO[j]);
            }
        }
        __syncthreads();   // protect KV buffer reuse (and probs before staging)
    }

    // stage 64x64 fp32 result over the (now dead) scores region, then half4 store
    float* St2 = f;          // [64][68]
#pragma unroll
    for (int j = 0; j < 2; j++)
        wmma::store_matrix_sync(St2 + (tm * 16) * 68 + tn * 32 + j * 16, accO[j],
                                68, wmma::mem_row_major);
    __syncthreads();
    for (int idx = tid; idx < QB * 16; idx += 256) {
        int r = idx >> 4, c = (idx & 15) * 4;
        float4 v = *reinterpret_cast<const float4*>(St2 + r * 68 + c);
        *reinterpret_cast<uint2*>(out + (size_t)(bv * Tc + q0 + r) * Dc + h * DHc + c) =
            pack_half4(v.x, v.y, v.z, v.w);
    }
}

// ---------------- launch ----------------
extern "C" void kernel_launch(void* const* d_in, const int* in_sizes, int n_in,
                              void* d_out, int out_size)
{
    const float* x  = (const float*)d_in[0];
    const int* mask = (const int*)d_in[1];          // bool -> int32 in harness
    const float* Wq = (const float*)d_in[2];
    const float* bq = (const float*)d_in[3];
    const float* Wk = (const float*)d_in[4];
    const float* bk = (const float*)d_in[5];
    const float* Wv = (const float*)d_in[6];
    const float* bvb = (const float*)d_in[7];
    const float* Wo = (const float*)d_in[8];
    const float* bo = (const float*)d_in[9];
    const float* W1 = (const float*)d_in[10];
    const float* b1 = (const float*)d_in[11];
    const float* W2 = (const float*)d_in[12];
    const float* b2 = (const float*)d_in[13];
    const float* g1 = (const float*)d_in[14];
    const float* be1 = (const float*)d_in[15];
    const float* g2 = (const float*)d_in[16];
    const float* be2 = (const float*)d_in[17];
    float* out = (float*)d_out;

    __half *xnh, *qh, *kh, *vh, *ath, *h2h, *ffh, *wqkv, *who, *wh1, *wh2;
    float *xr, *bqkv;
    cudaGetSymbolAddress((void**)&xnh,  g_xnh);
    cudaGetSymbolAddress((void**)&qh,   g_qh);
    cudaGetSymbolAddress((void**)&kh,   g_kh);
    cudaGetSymbolAddress((void**)&vh,   g_vh);
    cudaGetSymbolAddress((void**)&ath,  g_ath);
    cudaGetSymbolAddress((void**)&h2h,  g_h2h);
    cudaGetSymbolAddress((void**)&ffh,  g_ffh);
    cudaGetSymbolAddress((void**)&xr,   g_xr);
    cudaGetSymbolAddress((void**)&wqkv, g_wqkv);
    cudaGetSymbolAddress((void**)&bqkv, g_bqkv);
    cudaGetSymbolAddress((void**)&who,  g_who);
    cudaGetSymbolAddress((void**)&wh1,  g_wh1);
    cudaGetSymbolAddress((void**)&wh2,  g_wh2);

    cudaFuncSetAttribute(gemm_h<0>, cudaFuncAttributeMaxDynamicSharedMemorySize, (int)SMH);
    cudaFuncSetAttribute(gemm_h<1>, cudaFuncAttributeMaxDynamicSharedMemorySize, (int)SMH);
    cudaFuncSetAttribute(gemm_h<2>, cudaFuncAttributeMaxDynamicSharedMemorySize, (int)SMH);
    cudaFuncSetAttribute(gemm_h<3>, cudaFuncAttributeMaxDynamicSharedMemorySize, (int)SMH);
    cudaFuncSetAttribute(attn_kernel, cudaFuncAttributeMaxDynamicSharedMemorySize, (int)SMA);

    dim3 gqkv(3 * Dc / BN, MTOK / BM);   // (12, 768)
    dim3 g512(Dc / BN, MTOK / BM);       // (4, 768)
    dim3 gff(DFFc / BN, MTOK / BM);      // (16, 768)

    // launches 1-2: weight prep (merged; also positions oproj as launch #6 for ncu -s 5)
    wprep_qkv<<<3 * Dc * Dc / 4 / 256, 256>>>(Wq, Wk, Wv, bq, bk, bvb, wqkv, bqkv);
    {
        int n4 = (Dc * Dc + Dc * DFFc + DFFc * Dc) / 4;
        wprep_rest<<<(n4 + 255) / 256, 256>>>(Wo, W1, W2, who, wh1, wh2);
    }
    // 3: LN1 (gather-transpose from x) -> half
    ln_kernel<<<MTOK / 8, 256>>>(x, g1, be1, xnh, 1);
    // 4: merged QKV projection -> head-major half
    gemm_h<0><<<gqkv, 256, SMH>>>(xnh, wqkv, MTOK, 3 * Dc, Dc, bqkv, nullptr,
                                  nullptr, qh, kh, vh);
    // 5: Attention -> half (QB=64 tiles)
    attn_kernel<<<dim3(Tc / QB, Hc, BV), 256, SMA>>>(qh, kh, vh, mask, ath);
    // 6: O-projection + residual (x gathered) -> xr fp32   [ncu target]
    gemm_h<1><<<g512, 256, SMH>>>(ath, who, MTOK, Dc, Dc, bo, x, xr, nullptr,
                                  nullptr, nullptr);
    // 7: LN2 -> half
    ln_kernel<<<MTOK / 8, 256>>>(xr, g2, be2, h2h, 0);
    // 8: FFN1 + bias + exact gelu -> half
    gemm_h<2><<<gff, 256, SMH>>>(h2h, wh1, MTOK, DFFc, Dc, b1, nullptr,
                                 nullptr, ffh, nullptr, nullptr);
    // 9: FFN2 + bias + residual + scatter-transpose -> fp32 d_out
    gemm_h<3><<<g512, 256, SMH>>>(ffh, wh2, MTOK, Dc, DFFc, b2, xr, out,
                                  nullptr, nullptr, nullptr);
}